// round 5
// baseline (speedup 1.0000x reference)
#include <cuda_runtime.h>
#include <cstdint>

// Problem constants
#define NB   32
#define LQ   2048
#define LK   2048
#define DIN  32
#define DKQ  20
#define EPS  1e-5f
// fold 1/sqrt(20) * log2(e) into q so scores are in log2 domain
#define QSCALE 0.32258572299984063f   // log2(e)/sqrt(20)

#define KSTRIDE 28   // padded K feature stride
#define QSTRIDE 24   // padded Q feature stride (3 k8 chunks)
#define VSTRIDE 36   // padded V stride

#define NSPLIT 2
#define LKH  (LK / NSPLIT)

// Scratch (allocation-free rule: __device__ globals)
__device__ float d_vproj[(size_t)NB * LK * VSTRIDE];
__device__ float d_kproj[(size_t)NB * LK * KSTRIDE];
__device__ float d_qproj[(size_t)NB * LQ * QSTRIDE];
__device__ float d_po[(size_t)NSPLIT * NB * LQ * DIN]; // partial o sums
__device__ float d_pl[(size_t)NSPLIT * NB * LQ];       // partial l sums

typedef unsigned int u32;

__device__ __forceinline__ float tf32r(float x) {
    u32 u; asm("cvt.rna.tf32.f32 %0, %1;" : "=r"(u) : "f"(x));
    return __uint_as_float(u);
}
__device__ __forceinline__ float ex2f(float x) {
    float r; asm("ex2.approx.f32 %0, %1;" : "=f"(r) : "f"(x));
    return r;
}
// m16n8k8 tf32 mma: D = A*B + C  (fp32 accum)
__device__ __forceinline__ void mma_tf32(
    float& d0, float& d1, float& d2, float& d3,
    u32 a0, u32 a1, u32 a2, u32 a3, u32 b0, u32 b1,
    float c0, float c1, float c2, float c3)
{
    asm("mma.sync.aligned.m16n8k8.row.col.f32.tf32.tf32.f32 "
        "{%0,%1,%2,%3},{%4,%5,%6,%7},{%8,%9},{%10,%11,%12,%13};"
        : "=f"(d0), "=f"(d1), "=f"(d2), "=f"(d3)
        : "r"(a0), "r"(a1), "r"(a2), "r"(a3), "r"(b0), "r"(b1),
          "f"(c0), "f"(c1), "f"(c2), "f"(c3));
}

// ---------------------------------------------------------------------------
// Kernel 1: fused projections (tf32-rounded, padded strides)
// ---------------------------------------------------------------------------
__global__ __launch_bounds__(256) void proj_kernel(
    const float* __restrict__ vals, const float* __restrict__ keys,
    const float* __restrict__ ques,
    const float* __restrict__ Wv, const float* __restrict__ Wk, const float* __restrict__ Wq,
    const float* __restrict__ gk, const float* __restrict__ bk,
    const float* __restrict__ gq, const float* __restrict__ bq)
{
    __shared__ float sWv[DIN * DIN];
    __shared__ float sWk[DKQ * DIN];
    __shared__ float sWq[DKQ * DIN];
    __shared__ float sgk[DKQ], sbk[DKQ], sgq[DKQ], sbq[DKQ];

    int tid = threadIdx.x;
    for (int i = tid; i < DIN * DIN; i += 256) sWv[i] = Wv[i];
    for (int i = tid; i < DKQ * DIN; i += 256) sWk[i] = Wk[i];
    for (int i = tid; i < DKQ * DIN; i += 256) sWq[i] = Wq[i];
    if (tid < DKQ) { sgk[tid] = gk[tid]; sbk[tid] = bk[tid]; sgq[tid] = gq[tid]; sbq[tid] = bq[tid]; }
    __syncthreads();

    size_t r = (size_t)blockIdx.x * 256 + tid;

    float x[DIN];

    // ---- V projection (tf32-rounded, stride 36) ----
    {
        const float4* p4 = (const float4*)(vals + r * DIN);
        #pragma unroll
        for (int i = 0; i < 8; i++) {
            float4 t = p4[i];
            x[4*i] = t.x; x[4*i+1] = t.y; x[4*i+2] = t.z; x[4*i+3] = t.w;
        }
        float outr[DIN];
        #pragma unroll
        for (int o = 0; o < DIN; o++) {
            float acc = 0.f;
            #pragma unroll
            for (int d = 0; d < DIN; d++) acc += x[d] * sWv[o * DIN + d];
            outr[o] = tf32r(acc);
        }
        float4* o4 = (float4*)(d_vproj + r * VSTRIDE);
        #pragma unroll
        for (int i = 0; i < 8; i++)
            o4[i] = make_float4(outr[4*i], outr[4*i+1], outr[4*i+2], outr[4*i+3]);
        o4[8] = make_float4(0.f, 0.f, 0.f, 0.f);
    }

    // ---- K projection + LN (tf32, stride 28, zero pad) ----
    {
        const float4* p4 = (const float4*)(keys + r * DIN);
        #pragma unroll
        for (int i = 0; i < 8; i++) {
            float4 t = p4[i];
            x[4*i] = t.x; x[4*i+1] = t.y; x[4*i+2] = t.z; x[4*i+3] = t.w;
        }
        float y[DKQ];
        #pragma unroll
        for (int o = 0; o < DKQ; o++) {
            float acc = 0.f;
            #pragma unroll
            for (int d = 0; d < DIN; d++) acc += x[d] * sWk[o * DIN + d];
            y[o] = acc;
        }
        float m = 0.f;
        #pragma unroll
        for (int c = 0; c < DKQ; c++) m += y[c];
        m *= (1.f / DKQ);
        float v = 0.f;
        #pragma unroll
        for (int c = 0; c < DKQ; c++) { float d = y[c] - m; v += d * d; }
        v *= (1.f / DKQ);
        float rs = rsqrtf(v + EPS);
        #pragma unroll
        for (int c = 0; c < DKQ; c++) y[c] = tf32r((y[c] - m) * rs * sgk[c] + sbk[c]);
        float4* o4 = (float4*)(d_kproj + r * KSTRIDE);
        #pragma unroll
        for (int i = 0; i < 5; i++)
            o4[i] = make_float4(y[4*i], y[4*i+1], y[4*i+2], y[4*i+3]);
        o4[5] = make_float4(0.f, 0.f, 0.f, 0.f);
        o4[6] = make_float4(0.f, 0.f, 0.f, 0.f);
    }

    // ---- Q projection + LN + QSCALE (tf32, stride 24, zero pad) ----
    {
        const float4* p4 = (const float4*)(ques + r * DIN);
        #pragma unroll
        for (int i = 0; i < 8; i++) {
            float4 t = p4[i];
            x[4*i] = t.x; x[4*i+1] = t.y; x[4*i+2] = t.z; x[4*i+3] = t.w;
        }
        float y[DKQ];
        #pragma unroll
        for (int o = 0; o < DKQ; o++) {
            float acc = 0.f;
            #pragma unroll
            for (int d = 0; d < DIN; d++) acc += x[d] * sWq[o * DIN + d];
            y[o] = acc;
        }
        float m = 0.f;
        #pragma unroll
        for (int c = 0; c < DKQ; c++) m += y[c];
        m *= (1.f / DKQ);
        float v = 0.f;
        #pragma unroll
        for (int c = 0; c < DKQ; c++) { float d = y[c] - m; v += d * d; }
        v *= (1.f / DKQ);
        float rs = rsqrtf(v + EPS);
        #pragma unroll
        for (int c = 0; c < DKQ; c++)
            y[c] = tf32r(((y[c] - m) * rs * sgq[c] + sbq[c]) * QSCALE);
        float4* o4 = (float4*)(d_qproj + r * QSTRIDE);
        #pragma unroll
        for (int i = 0; i < 5; i++)
            o4[i] = make_float4(y[4*i], y[4*i+1], y[4*i+2], y[4*i+3]);
        o4[5] = make_float4(0.f, 0.f, 0.f, 0.f);
    }
}

// ---------------------------------------------------------------------------
// Kernel 2: split-K flash attention via mma.sync m16n8k8 tf32.
// CTA = 128 thr = 4 warps; warp: 32 queries (2 m16 tiles); CTA: 128 queries.
// grid = (LQ/128, NB, NSPLIT): each CTA covers LK/NSPLIT keys, emits partials.
// ---------------------------------------------------------------------------
#define TS 128

__global__ __launch_bounds__(128) void attn_partial_kernel(const void* __restrict__ mask_raw)
{
    __shared__ float sK[TS * KSTRIDE];   // 14336 B
    __shared__ float sV[TS * VSTRIDE];   // 18432 B
    __shared__ float sbias[TS];
    __shared__ int s_is_byte;

    int tid  = threadIdx.x;
    int w    = tid >> 5;
    int lane = tid & 31;
    int g    = lane >> 2;   // group id (0..7)
    int i    = lane & 3;    // thread in group (0..3)
    int b    = blockIdx.y;
    int h    = blockIdx.z;
    int qbase = blockIdx.x * 128 + w * 32;

    if (tid == 0) {
        // Detect mask storage: numpy bool (1 byte) vs int32 coercion.
        const unsigned int* wd = (const unsigned int*)mask_raw;
        unsigned int acc = 0;
        for (int k = 0; k < 64; k++) acc |= wd[k] & 0xFFFFFF00u;
        s_is_byte = (acc != 0u);
    }

    // ---- Q fragments: two m16 tiles, held in registers ----
    u32 aq[2][3][4];
    #pragma unroll
    for (int t = 0; t < 2; t++) {
        const float* q0p = d_qproj + ((size_t)b * LQ + qbase + t * 16 + g) * QSTRIDE;
        const float* q1p = q0p + 8 * QSTRIDE;
        #pragma unroll
        for (int c = 0; c < 3; c++) {
            aq[t][c][0] = __float_as_uint(q0p[c * 8 + i]);
            aq[t][c][1] = __float_as_uint(q1p[c * 8 + i]);
            aq[t][c][2] = __float_as_uint(q0p[c * 8 + i + 4]);
            aq[t][c][3] = __float_as_uint(q1p[c * 8 + i + 4]);
        }
    }

    float o[2][4][4];
    #pragma unroll
    for (int t = 0; t < 2; t++)
        #pragma unroll
        for (int nt = 0; nt < 4; nt++)
            #pragma unroll
            for (int r = 0; r < 4; r++) o[t][nt][r] = 0.f;
    float lac[2][2];
    lac[0][0] = lac[0][1] = lac[1][0] = lac[1][1] = 0.f;

    const float* kbase = d_kproj + ((size_t)b * LK + (size_t)h * LKH) * KSTRIDE;
    const float* vbase = d_vproj + ((size_t)b * LK + (size_t)h * LKH) * VSTRIDE;
    const unsigned char* mB = (const unsigned char*)mask_raw + (size_t)b * LK + (size_t)h * LKH;
    const int*           mI = (const int*)mask_raw + (size_t)b * LK + (size_t)h * LKH;

    for (int t0 = 0; t0 < LKH; t0 += TS) {
        __syncthreads();
        // ---- cooperative tile load (linear float4 copies) ----
        {
            const float4* kg = (const float4*)(kbase + (size_t)t0 * KSTRIDE);
            float4* ks4 = (float4*)sK;
            #pragma unroll
            for (int idx = tid; idx < TS * KSTRIDE / 4; idx += 128) ks4[idx] = kg[idx];
            const float4* vg = (const float4*)(vbase + (size_t)t0 * VSTRIDE);
            float4* vs4 = (float4*)sV;
            #pragma unroll
            for (int idx = tid; idx < TS * VSTRIDE / 4; idx += 128) vs4[idx] = vg[idx];
            int mv = s_is_byte ? (int)mB[t0 + tid] : mI[t0 + tid];
            sbias[tid] = mv ? -1e30f : 0.f;   // True masks OUT
        }
        __syncthreads();

        #pragma unroll 2
        for (int kc = 0; kc < TS / 8; kc++) {
            // shared-per-chunk operands
            float ba = sbias[kc * 8 + 2 * i];
            float bb = sbias[kc * 8 + 2 * i + 1];
            const float* kr = sK + (kc * 8 + g) * KSTRIDE;
            u32 kb[3][2];
            #pragma unroll
            for (int c = 0; c < 3; c++) {
                kb[c][0] = __float_as_uint(kr[c * 8 + i]);
                kb[c][1] = __float_as_uint(kr[c * 8 + i + 4]);
            }
            const float* vr0 = sV + (kc * 8 + 2 * i) * VSTRIDE;
            const float* vr1 = vr0 + VSTRIDE;
            u32 vb[4][2];
            #pragma unroll
            for (int nt = 0; nt < 4; nt++) {
                vb[nt][0] = __float_as_uint(vr0[nt * 8 + g]);
                vb[nt][1] = __float_as_uint(vr1[nt * 8 + g]);
            }

            // two independent M-tiles share the fragments
            #pragma unroll
            for (int t = 0; t < 2; t++) {
                float s0 = ba, s1 = bb, s2 = ba, s3 = bb;
                #pragma unroll
                for (int c = 0; c < 3; c++) {
                    mma_tf32(s0, s1, s2, s3,
                             aq[t][c][0], aq[t][c][1], aq[t][c][2], aq[t][c][3],
                             kb[c][0], kb[c][1], s0, s1, s2, s3);
                }
                float e0 = ex2f(s0);
                float e1 = ex2f(s1);
                float e2 = ex2f(s2);
                float e3 = ex2f(s3);
                lac[t][0] += e0 + e1;
                lac[t][1] += e2 + e3;
                // P frag: raw fp32 bits as tf32 (HW truncates mantissa)
                u32 p0 = __float_as_uint(e0);
                u32 p1 = __float_as_uint(e2);
                u32 p2 = __float_as_uint(e1);
                u32 p3 = __float_as_uint(e3);
                #pragma unroll
                for (int nt = 0; nt < 4; nt++) {
                    mma_tf32(o[t][nt][0], o[t][nt][1], o[t][nt][2], o[t][nt][3],
                             p0, p1, p2, p3, vb[nt][0], vb[nt][1],
                             o[t][nt][0], o[t][nt][1], o[t][nt][2], o[t][nt][3]);
                }
            }
        }
    }

    // ---- store partials (unnormalized o-sum and l-sum) ----
    size_t pbase = ((size_t)h * NB + b) * LQ;
    #pragma unroll
    for (int t = 0; t < 2; t++) {
        float l0 = lac[t][0], l1 = lac[t][1];
        l0 += __shfl_xor_sync(0xFFFFFFFFu, l0, 1);
        l0 += __shfl_xor_sync(0xFFFFFFFFu, l0, 2);
        l1 += __shfl_xor_sync(0xFFFFFFFFu, l1, 1);
        l1 += __shfl_xor_sync(0xFFFFFFFFu, l1, 2);

        #pragma unroll
        for (int half = 0; half < 2; half++) {
            int row = qbase + t * 16 + g + half * 8;
            int r0  = half == 0 ? 0 : 2;
            float2* po = (float2*)(d_po + (pbase + row) * DIN);
            #pragma unroll
            for (int nt = 0; nt < 4; nt++) {
                float2 tt;
                tt.x = o[t][nt][r0];
                tt.y = o[t][nt][r0 + 1];
                po[nt * 4 + i] = tt;
            }
            if (i == 0) d_pl[pbase + row] = half == 0 ? l0 : l1;
        }
    }
}

// ---------------------------------------------------------------------------
// Kernel 3: combine partials + residual + final LayerNorm. One thread per row.
// ---------------------------------------------------------------------------
__global__ __launch_bounds__(256) void combine_kernel(
    const float* __restrict__ ques,
    const float* __restrict__ go, const float* __restrict__ bo,
    float* __restrict__ out)
{
    __shared__ float sgo[DIN], sbo[DIN];
    int tid = threadIdx.x;
    if (tid < DIN) { sgo[tid] = go[tid]; sbo[tid] = bo[tid]; }
    __syncthreads();

    size_t r = (size_t)blockIdx.x * 256 + tid;          // row in [0, NB*LQ)
    const size_t half = (size_t)NB * LQ;

    float l = d_pl[r] + d_pl[half + r];
    float invl = 1.f / l;

    const float4* a4 = (const float4*)(d_po + r * DIN);
    const float4* b4 = (const float4*)(d_po + (half + r) * DIN);
    const float4* q4 = (const float4*)(ques + r * DIN);

    float tv[DIN];
    #pragma unroll
    for (int i = 0; i < 8; i++) {
        float4 a = a4[i], b = b4[i], q = q4[i];
        tv[4*i]   = (a.x + b.x) * invl + q.x;
        tv[4*i+1] = (a.y + b.y) * invl + q.y;
        tv[4*i+2] = (a.z + b.z) * invl + q.z;
        tv[4*i+3] = (a.w + b.w) * invl + q.w;
    }

    float m = 0.f;
    #pragma unroll
    for (int c = 0; c < DIN; c++) m += tv[c];
    m *= (1.f / DIN);
    float v = 0.f;
    #pragma unroll
    for (int c = 0; c < DIN; c++) { float d = tv[c] - m; v += d * d; }
    v *= (1.f / DIN);
    float rs = rsqrtf(v + EPS);

    float4* po = (float4*)(out + r * DIN);
    #pragma unroll
    for (int i = 0; i < 8; i++) {
        float4 t;
        t.x = (tv[4*i]   - m) * rs * sgo[4*i]   + sbo[4*i];
        t.y = (tv[4*i+1] - m) * rs * sgo[4*i+1] + sbo[4*i+1];
        t.z = (tv[4*i+2] - m) * rs * sgo[4*i+2] + sbo[4*i+2];
        t.w = (tv[4*i+3] - m) * rs * sgo[4*i+3] + sbo[4*i+3];
        po[i] = t;
    }
}

// ---------------------------------------------------------------------------
extern "C" void kernel_launch(void* const* d_in, const int* in_sizes, int n_in,
                              void* d_out, int out_size)
{
    const float* vals = (const float*)d_in[0];
    const float* keys = (const float*)d_in[1];
    const float* ques = (const float*)d_in[2];
    const void*  mask = d_in[3];
    const float* Wv   = (const float*)d_in[4];
    const float* Wk   = (const float*)d_in[5];
    const float* Wq   = (const float*)d_in[6];
    const float* gk   = (const float*)d_in[7];
    const float* bk   = (const float*)d_in[8];
    const float* gq   = (const float*)d_in[9];
    const float* bq   = (const float*)d_in[10];
    const float* go   = (const float*)d_in[11];
    const float* bo   = (const float*)d_in[12];
    float* out = (float*)d_out;

    proj_kernel<<<(NB * LK) / 256, 256>>>(vals, keys, ques, Wv, Wk, Wq, gk, bk, gq, bq);

    dim3 grid(LQ / 128, NB, NSPLIT);
    attn_partial_kernel<<<grid, 128>>>(mask);

    combine_kernel<<<(NB * LQ) / 256, 256>>>(ques, go, bo, out);
}

// round 6
// speedup vs baseline: 1.0872x; 1.0872x over previous
#include <cuda_runtime.h>
#include <cstdint>

// Problem constants
#define NB   32
#define LQ   2048
#define LK   2048
#define DIN  32
#define DKQ  20
#define EPS  1e-5f
// fold 1/sqrt(20) * log2(e) into q so scores are in log2 domain
#define QSCALE 0.32258572299984063f   // log2(e)/sqrt(20)

#define KSTRIDE 28   // padded K feature stride
#define QSTRIDE 24   // padded Q feature stride (3 k8 chunks)
#define VSTRIDE 36   // padded V stride

// Scratch (allocation-free rule: __device__ globals)
__device__ float d_vproj[(size_t)NB * LK * VSTRIDE];
__device__ float d_kproj[(size_t)NB * LK * KSTRIDE];
__device__ float d_qproj[(size_t)NB * LQ * QSTRIDE];

typedef unsigned int u32;

__device__ __forceinline__ float tf32r(float x) {
    u32 u; asm("cvt.rna.tf32.f32 %0, %1;" : "=r"(u) : "f"(x));
    return __uint_as_float(u);
}
__device__ __forceinline__ float ex2f(float x) {
    float r; asm("ex2.approx.f32 %0, %1;" : "=f"(r) : "f"(x));
    return r;
}
// m16n8k8 tf32 mma: D = A*B + C  (fp32 accum)
__device__ __forceinline__ void mma_tf32(
    float& d0, float& d1, float& d2, float& d3,
    u32 a0, u32 a1, u32 a2, u32 a3, u32 b0, u32 b1,
    float c0, float c1, float c2, float c3)
{
    asm("mma.sync.aligned.m16n8k8.row.col.f32.tf32.tf32.f32 "
        "{%0,%1,%2,%3},{%4,%5,%6,%7},{%8,%9},{%10,%11,%12,%13};"
        : "=f"(d0), "=f"(d1), "=f"(d2), "=f"(d3)
        : "r"(a0), "r"(a1), "r"(a2), "r"(a3), "r"(b0), "r"(b1),
          "f"(c0), "f"(c1), "f"(c2), "f"(c3));
}
__device__ __forceinline__ void cp16(u32 dst, const void* src) {
    asm volatile("cp.async.cg.shared.global [%0], [%1], 16;" :: "r"(dst), "l"(src));
}
#define CP_COMMIT() asm volatile("cp.async.commit_group;")
#define CP_WAIT0()  asm volatile("cp.async.wait_group 0;")

// ---------------------------------------------------------------------------
// Kernel 1: projections, split 3 ways by blockIdx.y (0=V, 1=K, 2=Q).
// One thread per (row, task). grid = (256, 3) x 256 thr.
// ---------------------------------------------------------------------------
__global__ __launch_bounds__(256) void proj_kernel(
    const float* __restrict__ vals, const float* __restrict__ keys,
    const float* __restrict__ ques,
    const float* __restrict__ Wv, const float* __restrict__ Wk, const float* __restrict__ Wq,
    const float* __restrict__ gk, const float* __restrict__ bk,
    const float* __restrict__ gq, const float* __restrict__ bq)
{
    __shared__ float sW[DIN * DIN];
    __shared__ float sg[DKQ], sb[DKQ];

    int tid  = threadIdx.x;
    int task = blockIdx.y;
    size_t r = (size_t)blockIdx.x * 256 + tid;

    if (task == 0) {
        for (int i = tid; i < DIN * DIN; i += 256) sW[i] = Wv[i];
        __syncthreads();

        float x[DIN];
        const float4* p4 = (const float4*)(vals + r * DIN);
        #pragma unroll
        for (int i = 0; i < 8; i++) {
            float4 t = p4[i];
            x[4*i] = t.x; x[4*i+1] = t.y; x[4*i+2] = t.z; x[4*i+3] = t.w;
        }
        float outr[DIN];
        #pragma unroll
        for (int o = 0; o < DIN; o++) {
            float acc = 0.f;
            #pragma unroll
            for (int d = 0; d < DIN; d++) acc += x[d] * sW[o * DIN + d];
            outr[o] = tf32r(acc);
        }
        float4* o4 = (float4*)(d_vproj + r * VSTRIDE);
        #pragma unroll
        for (int i = 0; i < 8; i++)
            o4[i] = make_float4(outr[4*i], outr[4*i+1], outr[4*i+2], outr[4*i+3]);
        o4[8] = make_float4(0.f, 0.f, 0.f, 0.f);
    } else {
        const float* W  = (task == 1) ? Wk : Wq;
        const float* gg = (task == 1) ? gk : gq;
        const float* bb = (task == 1) ? bk : bq;
        const float* in = (task == 1) ? keys : ques;
        for (int i = tid; i < DKQ * DIN; i += 256) sW[i] = W[i];
        if (tid < DKQ) { sg[tid] = gg[tid]; sb[tid] = bb[tid]; }
        __syncthreads();

        float x[DIN];
        const float4* p4 = (const float4*)(in + r * DIN);
        #pragma unroll
        for (int i = 0; i < 8; i++) {
            float4 t = p4[i];
            x[4*i] = t.x; x[4*i+1] = t.y; x[4*i+2] = t.z; x[4*i+3] = t.w;
        }
        float y[DKQ];
        #pragma unroll
        for (int o = 0; o < DKQ; o++) {
            float acc = 0.f;
            #pragma unroll
            for (int d = 0; d < DIN; d++) acc += x[d] * sW[o * DIN + d];
            y[o] = acc;
        }
        float m = 0.f;
        #pragma unroll
        for (int c = 0; c < DKQ; c++) m += y[c];
        m *= (1.f / DKQ);
        float v = 0.f;
        #pragma unroll
        for (int c = 0; c < DKQ; c++) { float d = y[c] - m; v += d * d; }
        v *= (1.f / DKQ);
        float rs = rsqrtf(v + EPS);

        if (task == 1) {
            #pragma unroll
            for (int c = 0; c < DKQ; c++) y[c] = tf32r((y[c] - m) * rs * sg[c] + sb[c]);
            float4* o4 = (float4*)(d_kproj + r * KSTRIDE);
            #pragma unroll
            for (int i = 0; i < 5; i++)
                o4[i] = make_float4(y[4*i], y[4*i+1], y[4*i+2], y[4*i+3]);
            o4[5] = make_float4(0.f, 0.f, 0.f, 0.f);
            o4[6] = make_float4(0.f, 0.f, 0.f, 0.f);
        } else {
            #pragma unroll
            for (int c = 0; c < DKQ; c++)
                y[c] = tf32r(((y[c] - m) * rs * sg[c] + sb[c]) * QSCALE);
            float4* o4 = (float4*)(d_qproj + r * QSTRIDE);
            #pragma unroll
            for (int i = 0; i < 5; i++)
                o4[i] = make_float4(y[4*i], y[4*i+1], y[4*i+2], y[4*i+3]);
            o4[5] = make_float4(0.f, 0.f, 0.f, 0.f);
        }
    }
}

// ---------------------------------------------------------------------------
// Kernel 2: flash attention, mma.sync m16n8k8 tf32, cp.async double-buffered
// K/V tiles. CTA = 128 thr = 4 warps; warp: 32 queries; CTA: 128 queries.
// grid = (LQ/128, NB).
// ---------------------------------------------------------------------------
#define TS 128
#define NT (LK / TS)

__global__ __launch_bounds__(128) void attn_kernel(
    const void* __restrict__ mask_raw, const float* __restrict__ ques,
    const float* __restrict__ go, const float* __restrict__ bo,
    float* __restrict__ out)
{
    __shared__ float sK[2][TS * KSTRIDE];   // 2 x 14336 B
    __shared__ float sV[2][TS * VSTRIDE];   // 2 x 18432 B
    __shared__ float sbias[2][TS];
    __shared__ int s_is_byte;

    int tid  = threadIdx.x;
    int w    = tid >> 5;
    int lane = tid & 31;
    int g    = lane >> 2;   // group id (0..7)
    int i    = lane & 3;    // thread in group (0..3)
    int b    = blockIdx.y;
    int qbase = blockIdx.x * 128 + w * 32;

    if (tid == 0) {
        // Detect mask storage: numpy bool (1 byte) vs int32 coercion.
        const unsigned int* wd = (const unsigned int*)mask_raw;
        unsigned int acc = 0;
        for (int k = 0; k < 64; k++) acc |= wd[k] & 0xFFFFFF00u;
        s_is_byte = (acc != 0u);
    }

    // ---- Q fragments: two m16 tiles, held in registers ----
    u32 aq[2][3][4];
    #pragma unroll
    for (int t = 0; t < 2; t++) {
        const float* q0p = d_qproj + ((size_t)b * LQ + qbase + t * 16 + g) * QSTRIDE;
        const float* q1p = q0p + 8 * QSTRIDE;
        #pragma unroll
        for (int c = 0; c < 3; c++) {
            aq[t][c][0] = __float_as_uint(q0p[c * 8 + i]);
            aq[t][c][1] = __float_as_uint(q1p[c * 8 + i]);
            aq[t][c][2] = __float_as_uint(q0p[c * 8 + i + 4]);
            aq[t][c][3] = __float_as_uint(q1p[c * 8 + i + 4]);
        }
    }

    float o[2][4][4];
    #pragma unroll
    for (int t = 0; t < 2; t++)
        #pragma unroll
        for (int nt = 0; nt < 4; nt++)
            #pragma unroll
            for (int r = 0; r < 4; r++) o[t][nt][r] = 0.f;
    float lac[2][2];
    lac[0][0] = lac[0][1] = lac[1][0] = lac[1][1] = 0.f;

    const float* kbase = d_kproj + (size_t)b * LK * KSTRIDE;
    const float* vbase = d_vproj + (size_t)b * LK * VSTRIDE;
    const unsigned char* mB = (const unsigned char*)mask_raw + (size_t)b * LK;
    const int*           mI = (const int*)mask_raw + (size_t)b * LK;

    __syncthreads();   // s_is_byte visible
    int is_byte = s_is_byte;

    // ---- preamble: async load tile 0, bias 0 ----
    {
        u32 k_u = (u32)__cvta_generic_to_shared(&sK[0][0]);
        u32 v_u = (u32)__cvta_generic_to_shared(&sV[0][0]);
        const float* kg = kbase;
        const float* vg = vbase;
        #pragma unroll
        for (int rr = 0; rr < 7; rr++)
            cp16(k_u + (tid + rr * 128) * 16, kg + (tid + rr * 128) * 4);
        #pragma unroll
        for (int rr = 0; rr < 9; rr++)
            cp16(v_u + (tid + rr * 128) * 16, vg + (tid + rr * 128) * 4);
        CP_COMMIT();
        int mv = is_byte ? (int)mB[tid] : mI[tid];
        sbias[0][tid] = mv ? -1e30f : 0.f;   // True masks OUT
    }

    for (int t0 = 0; t0 < NT; t0++) {
        int cur = t0 & 1;
        CP_WAIT0();
        __syncthreads();   // tile t0 ready; all warps done with buffer we refill

        // prefetch tile t0+1 (overlaps with compute below)
        int mvn = 0;
        if (t0 + 1 < NT) {
            int nxt = cur ^ 1;
            u32 k_u = (u32)__cvta_generic_to_shared(&sK[nxt][0]);
            u32 v_u = (u32)__cvta_generic_to_shared(&sV[nxt][0]);
            const float* kg = kbase + (size_t)(t0 + 1) * TS * KSTRIDE;
            const float* vg = vbase + (size_t)(t0 + 1) * TS * VSTRIDE;
            #pragma unroll
            for (int rr = 0; rr < 7; rr++)
                cp16(k_u + (tid + rr * 128) * 16, kg + (tid + rr * 128) * 4);
            #pragma unroll
            for (int rr = 0; rr < 9; rr++)
                cp16(v_u + (tid + rr * 128) * 16, vg + (tid + rr * 128) * 4);
            CP_COMMIT();
            int mloc = (t0 + 1) * TS + tid;
            mvn = is_byte ? (int)mB[mloc] : mI[mloc];
            sbias[cur ^ 1][tid] = mvn ? -1e30f : 0.f;
        }

        #pragma unroll 2
        for (int kc = 0; kc < TS / 8; kc++) {
            // shared-per-chunk operands
            float ba = sbias[cur][kc * 8 + 2 * i];
            float bb = sbias[cur][kc * 8 + 2 * i + 1];
            const float* kr = sK[cur] + (kc * 8 + g) * KSTRIDE;
            u32 kb[3][2];
            #pragma unroll
            for (int c = 0; c < 3; c++) {
                kb[c][0] = __float_as_uint(kr[c * 8 + i]);
                kb[c][1] = __float_as_uint(kr[c * 8 + i + 4]);
            }
            const float* vr0 = sV[cur] + (kc * 8 + 2 * i) * VSTRIDE;
            const float* vr1 = vr0 + VSTRIDE;
            u32 vb[4][2];
            #pragma unroll
            for (int nt = 0; nt < 4; nt++) {
                vb[nt][0] = __float_as_uint(vr0[nt * 8 + g]);
                vb[nt][1] = __float_as_uint(vr1[nt * 8 + g]);
            }

            // two independent M-tiles share the fragments
            #pragma unroll
            for (int t = 0; t < 2; t++) {
                float s0 = ba, s1 = bb, s2 = ba, s3 = bb;
                #pragma unroll
                for (int c = 0; c < 3; c++) {
                    mma_tf32(s0, s1, s2, s3,
                             aq[t][c][0], aq[t][c][1], aq[t][c][2], aq[t][c][3],
                             kb[c][0], kb[c][1], s0, s1, s2, s3);
                }
                float e0 = ex2f(s0);
                float e1 = ex2f(s1);
                float e2 = ex2f(s2);
                float e3 = ex2f(s3);
                lac[t][0] += e0 + e1;
                lac[t][1] += e2 + e3;
                // P frag: raw fp32 bits as tf32 (HW truncates mantissa)
                u32 p0 = __float_as_uint(e0);
                u32 p1 = __float_as_uint(e2);
                u32 p2 = __float_as_uint(e1);
                u32 p3 = __float_as_uint(e3);
                #pragma unroll
                for (int nt = 0; nt < 4; nt++) {
                    mma_tf32(o[t][nt][0], o[t][nt][1], o[t][nt][2], o[t][nt][3],
                             p0, p1, p2, p3, vb[nt][0], vb[nt][1],
                             o[t][nt][0], o[t][nt][1], o[t][nt][2], o[t][nt][3]);
                }
            }
        }
    }

    // ---- epilogue: reduce l, normalize, residual, LayerNorm, store ----
    #pragma unroll
    for (int t = 0; t < 2; t++) {
        float l0 = lac[t][0], l1 = lac[t][1];
        l0 += __shfl_xor_sync(0xFFFFFFFFu, l0, 1);
        l0 += __shfl_xor_sync(0xFFFFFFFFu, l0, 2);
        l1 += __shfl_xor_sync(0xFFFFFFFFu, l1, 1);
        l1 += __shfl_xor_sync(0xFFFFFFFFu, l1, 2);
        float inv0 = 1.f / l0;
        float inv1 = 1.f / l1;

        #pragma unroll
        for (int half = 0; half < 2; half++) {
            int   row  = qbase + t * 16 + g + half * 8;
            float invl = half == 0 ? inv0 : inv1;
            int   r0   = half == 0 ? 0 : 2;

            const float2* qr = (const float2*)(ques + ((size_t)b * LQ + row) * DIN);
            float x[4][2];
            float s = 0.f;
            #pragma unroll
            for (int nt = 0; nt < 4; nt++) {
                float2 qv = qr[nt * 4 + i];
                x[nt][0] = o[t][nt][r0]     * invl + qv.x;
                x[nt][1] = o[t][nt][r0 + 1] * invl + qv.y;
                s += x[nt][0] + x[nt][1];
            }
            s += __shfl_xor_sync(0xFFFFFFFFu, s, 1);
            s += __shfl_xor_sync(0xFFFFFFFFu, s, 2);
            float m = s * (1.f / DIN);
            float v = 0.f;
            #pragma unroll
            for (int nt = 0; nt < 4; nt++) {
                float d0 = x[nt][0] - m, d1 = x[nt][1] - m;
                v += d0 * d0 + d1 * d1;
            }
            v += __shfl_xor_sync(0xFFFFFFFFu, v, 1);
            v += __shfl_xor_sync(0xFFFFFFFFu, v, 2);
            float rs = rsqrtf(v * (1.f / DIN) + EPS);

            float2* po = (float2*)(out + ((size_t)b * LQ + row) * DIN);
            #pragma unroll
            for (int nt = 0; nt < 4; nt++) {
                int col = nt * 8 + 2 * i;
                float2 tt;
                tt.x = (x[nt][0] - m) * rs * __ldg(go + col)     + __ldg(bo + col);
                tt.y = (x[nt][1] - m) * rs * __ldg(go + col + 1) + __ldg(bo + col + 1);
                po[nt * 4 + i] = tt;
            }
        }
    }
}

// ---------------------------------------------------------------------------
extern "C" void kernel_launch(void* const* d_in, const int* in_sizes, int n_in,
                              void* d_out, int out_size)
{
    const float* vals = (const float*)d_in[0];
    const float* keys = (const float*)d_in[1];
    const float* ques = (const float*)d_in[2];
    const void*  mask = d_in[3];
    const float* Wv   = (const float*)d_in[4];
    const float* Wk   = (const float*)d_in[5];
    const float* Wq   = (const float*)d_in[6];
    const float* gk   = (const float*)d_in[7];
    const float* bk   = (const float*)d_in[8];
    const float* gq   = (const float*)d_in[9];
    const float* bq   = (const float*)d_in[10];
    const float* go   = (const float*)d_in[11];
    const float* bo   = (const float*)d_in[12];
    float* out = (float*)d_out;

    dim3 pgrid((NB * LK) / 256, 3);
    proj_kernel<<<pgrid, 256>>>(vals, keys, ques, Wv, Wk, Wq, gk, bk, gq, bq);

    dim3 grid(LQ / 128, NB);
    attn_kernel<<<grid, 128>>>(mask, ques, go, bo, out);
}